// round 1
// baseline (speedup 1.0000x reference)
#include <cuda_runtime.h>
#include <cstdint>

#define BB 16
#define TT 2048
#define HH 512
#define MM 96
#define VV 625
#define NL (BB*MM*MM*VV)   /* 92,160,000 logits */
#define NM (BB*MM*MM)      /* 147,456 mask entries */

// Scratch for projected q/k: [B*M, H] each (3 MB each) — device globals (no allocs).
__device__ float g_q[BB*MM*HH];
__device__ float g_k[BB*MM*HH];

// ---------------- packed f32x2 helpers (sm_103a FFMA2 path) ----------------
__device__ __forceinline__ unsigned long long dup_f32x2(float a) {
    unsigned long long r;
    asm("mov.b64 %0, {%1, %1};" : "=l"(r) : "f"(a));
    return r;
}
__device__ __forceinline__ void fma2(unsigned long long &acc,
                                     unsigned long long a, unsigned long long b) {
    asm("fma.rn.f32x2 %0, %1, %2, %0;" : "+l"(acc) : "l"(a), "l"(b));
}
__device__ __forceinline__ float2 unpack2(unsigned long long v) {
    float2 r;
    asm("mov.b64 {%0, %1}, %2;" : "=f"(r.x), "=f"(r.y) : "l"(v));
    return r;
}

// ---------------------------------------------------------------------------
// Stage A: gather masked tokens + bias-free q/k projections.
// Q[r,o] = sum_h x[b, idx[r], h] * Wq[o,h];  K likewise. r = b*M+m, R=1536.
// Tile 64 rows x 64 cols, both W matrices share the gathered X tile.
// ---------------------------------------------------------------------------
__global__ __launch_bounds__(256) void proj_kernel(
    const float* __restrict__ x, const float* __restrict__ Wq,
    const float* __restrict__ Wk, const int* __restrict__ midx)
{
    __shared__ float sX [32][68];
    __shared__ float sWq[32][68];
    __shared__ float sWk[32][68];

    const int tid = threadIdx.x;
    const int tx = tid & 15, ty = tid >> 4;
    const int r0 = blockIdx.x * 64;
    const int o0 = blockIdx.y * 64;

    float aq[4][4] = {};
    float ak[4][4] = {};

    // Precompute gather base for the 2 X float4s this thread loads per k-tile.
    size_t xbase[2];
    int lrow[2], lkk4[2];
    #pragma unroll
    for (int t = 0; t < 2; t++) {
        int idx = tid + t * 256;          // 0..511 -> 64 rows x 8 float4
        int row = idx >> 3, kk4 = idx & 7;
        lrow[t] = row; lkk4[t] = kk4;
        int rb  = r0 + row;
        int b   = rb / MM;
        int tok = midx[rb];
        xbase[t] = ((size_t)b * TT + tok) * HH + kk4 * 4;
    }

    for (int h0 = 0; h0 < HH; h0 += 32) {
        #pragma unroll
        for (int t = 0; t < 2; t++) {
            int row = lrow[t], kk = lkk4[t] * 4;
            float4 v = *(const float4*)(x + xbase[t] + h0);
            sX[kk+0][row] = v.x; sX[kk+1][row] = v.y;
            sX[kk+2][row] = v.z; sX[kk+3][row] = v.w;
            int o = o0 + row;
            float4 wq = *(const float4*)(Wq + (size_t)o * HH + h0 + lkk4[t] * 4);
            sWq[kk+0][row] = wq.x; sWq[kk+1][row] = wq.y;
            sWq[kk+2][row] = wq.z; sWq[kk+3][row] = wq.w;
            float4 wk = *(const float4*)(Wk + (size_t)o * HH + h0 + lkk4[t] * 4);
            sWk[kk+0][row] = wk.x; sWk[kk+1][row] = wk.y;
            sWk[kk+2][row] = wk.z; sWk[kk+3][row] = wk.w;
        }
        __syncthreads();
        #pragma unroll
        for (int kk = 0; kk < 32; kk++) {
            float4 xa = *(const float4*)&sX [kk][ty*4];
            float4 wq = *(const float4*)&sWq[kk][tx*4];
            float4 wk = *(const float4*)&sWk[kk][tx*4];
            float xr[4] = {xa.x, xa.y, xa.z, xa.w};
            float qr[4] = {wq.x, wq.y, wq.z, wq.w};
            float kr[4] = {wk.x, wk.y, wk.z, wk.w};
            #pragma unroll
            for (int r = 0; r < 4; r++)
                #pragma unroll
                for (int c = 0; c < 4; c++) {
                    aq[r][c] += xr[r] * qr[c];
                    ak[r][c] += xr[r] * kr[c];
                }
        }
        __syncthreads();
    }

    #pragma unroll
    for (int r = 0; r < 4; r++) {
        size_t row = (size_t)(r0 + ty*4 + r);
        float4 vq = make_float4(aq[r][0], aq[r][1], aq[r][2], aq[r][3]);
        float4 vk = make_float4(ak[r][0], ak[r][1], ak[r][2], ak[r][3]);
        *(float4*)(g_q + row * HH + o0 + tx*4) = vq;
        *(float4*)(g_k + row * HH + o0 + tx*4) = vk;
    }
}

// ---------------------------------------------------------------------------
// Stage B: fused pair-logits. One CTA = (b, i, v-tile of 128).
// A[j,h] = k[b,j,h] * q[b,i,h] formed during SMEM fill (amortized over v-tile).
// 96(j) x 128(v) tile, 192 threads, 8x8 micro-tile, FFMA2 (f32x2) inner loop.
// ---------------------------------------------------------------------------
__global__ __launch_bounds__(192, 2) void pair_kernel(
    const float* __restrict__ Wout, float* __restrict__ out)
{
    __shared__ float qs[HH];
    __shared__ float sA[32][100];   // [kk][j]  pad 100: STS 4-way max, LDS clean
    __shared__ float sB[32][132];   // [kk][v]  pad 132 (16B-aligned rows)

    const int tid = threadIdx.x;
    const int tx = tid & 15;        // v dim: 4+4 split columns
    const int ty = tid >> 4;        // j dim: 8 rows, ty in 0..11
    const int v0 = blockIdx.x * 128;
    const int i  = blockIdx.y;
    const int b  = blockIdx.z;

    const float* kb = g_k + (size_t)b * MM * HH;
    const float* qi = g_q + (size_t)(b * MM + i) * HH;

    for (int idx = tid; idx < HH; idx += 192) qs[idx] = qi[idx];
    __syncthreads();

    unsigned long long acc[8][4];
    #pragma unroll
    for (int r = 0; r < 8; r++)
        #pragma unroll
        for (int p = 0; p < 4; p++) acc[r][p] = 0ull;

    for (int h0 = 0; h0 < HH; h0 += 32) {
        // A tile: 96 rows x 32 h = 768 float4, scaled by q on the fly
        #pragma unroll
        for (int t = 0; t < 4; t++) {
            int idx = tid + t * 192;
            int j = idx >> 3, kk4 = idx & 7;
            float4 kv = *(const float4*)(kb + (size_t)j * HH + h0 + kk4 * 4);
            float4 qv = *(const float4*)&qs[h0 + kk4 * 4];
            int kk = kk4 * 4;
            sA[kk+0][j] = kv.x * qv.x;
            sA[kk+1][j] = kv.y * qv.y;
            sA[kk+2][j] = kv.z * qv.z;
            sA[kk+3][j] = kv.w * qv.w;
        }
        // B tile: 128 rows(v) x 32 h = 1024 float4, zero-fill past V2
        #pragma unroll
        for (int t = 0; t < 6; t++) {
            int idx = tid + t * 192;
            if (idx < 1024) {
                int v = idx >> 3, kk4 = idx & 7;
                int kk = kk4 * 4;
                if (v0 + v < VV) {
                    float4 wv = *(const float4*)(Wout + (size_t)(v0 + v) * HH + h0 + kk4 * 4);
                    sB[kk+0][v] = wv.x; sB[kk+1][v] = wv.y;
                    sB[kk+2][v] = wv.z; sB[kk+3][v] = wv.w;
                } else {
                    sB[kk+0][v] = 0.f; sB[kk+1][v] = 0.f;
                    sB[kk+2][v] = 0.f; sB[kk+3][v] = 0.f;
                }
            }
        }
        __syncthreads();

        #pragma unroll
        for (int kk = 0; kk < 32; kk++) {
            float4 a0 = *(const float4*)&sA[kk][ty*8];
            float4 a1 = *(const float4*)&sA[kk][ty*8 + 4];
            ulonglong2 bb0 = *(const ulonglong2*)&sB[kk][tx*4];        // v pairs (0,1),(2,3)
            ulonglong2 bb1 = *(const ulonglong2*)&sB[kk][64 + tx*4];   // +64 split
            float ar[8] = {a0.x, a0.y, a0.z, a0.w, a1.x, a1.y, a1.z, a1.w};
            #pragma unroll
            for (int r = 0; r < 8; r++) {
                unsigned long long ad = dup_f32x2(ar[r]);
                fma2(acc[r][0], ad, bb0.x);
                fma2(acc[r][1], ad, bb0.y);
                fma2(acc[r][2], ad, bb1.x);
                fma2(acc[r][3], ad, bb1.y);
            }
        }
        __syncthreads();
    }

    // Epilogue: logits row n = (b*M + i)*M + j, col v (scalar stores; V2=625 odd)
    const size_t nbase = (size_t)(b * MM + i) * MM;
    #pragma unroll
    for (int r = 0; r < 8; r++) {
        int j = ty * 8 + r;
        float* orow = out + (nbase + j) * VV;
        #pragma unroll
        for (int p = 0; p < 4; p++) {
            float2 val = unpack2(acc[r][p]);
            int v = v0 + ((p < 2) ? (tx*4 + p*2) : (64 + tx*4 + (p-2)*2));
            if (v     < VV) orow[v]     = val.x;
            if (v + 1 < VV) orow[v + 1] = val.y;
        }
    }
}

// ---------------------------------------------------------------------------
// diag_mask: tile(eye(M).flatten(), B) -> 1.0f where i==j
// ---------------------------------------------------------------------------
__global__ void mask_kernel(float* __restrict__ out, int n)
{
    int t = blockIdx.x * blockDim.x + threadIdx.x;
    if (t < n) {
        int i = (t / MM) % MM;
        int j = t % MM;
        out[t] = (i == j) ? 1.0f : 0.0f;
    }
}

extern "C" void kernel_launch(void* const* d_in, const int* in_sizes, int n_in,
                              void* d_out, int out_size)
{
    const float* x    = (const float*)d_in[0];
    const float* Wq   = (const float*)d_in[1];
    const float* Wk   = (const float*)d_in[2];
    const float* Wout = (const float*)d_in[3];
    const int*   midx = (const int*)  d_in[4];
    float* out = (float*)d_out;

    proj_kernel<<<dim3(24, 8), 256>>>(x, Wq, Wk, midx);
    pair_kernel<<<dim3(5, MM, BB), 192>>>(Wout, out);

    long long rem = (long long)out_size - (long long)NL;
    if (rem > 0) {
        int n = (int)rem;  // expected NM = 147456 (mask appended after logits)
        mask_kernel<<<(n + 255) / 256, 256>>>(out + (size_t)NL, n);
    }
}